// round 1
// baseline (speedup 1.0000x reference)
#include <cuda_runtime.h>

// Reverse cummax along axis 1 of [B=16, H=128, W=128, C=256] fp32.
// One thread per (b, w, c4) column (float4 over C). Walk h backward keeping
// a running max. Coalesced across C; streaming, bandwidth-bound.

static constexpr int B = 16;
static constexpr int H = 128;
static constexpr int W = 128;
static constexpr int C = 256;
static constexpr int C4 = C / 4;            // 64 float4 per row
static constexpr int STRIDE_H = W * C4;     // 8192 float4 between h slices
static constexpr int COLS = B * W * C4;     // 131072 columns
static constexpr int PER_B = W * C4;        // 8192 columns per batch
static constexpr long PER_B_ELEMS = (long)H * W * C4;  // 1048576 float4 per batch

__global__ void __launch_bounds__(256) rev_cummax_kernel(
    const float4* __restrict__ in, float4* __restrict__ out)
{
    int col = blockIdx.x * blockDim.x + threadIdx.x;
    if (col >= COLS) return;

    int b   = col >> 13;            // col / 8192
    int rem = col & (PER_B - 1);    // (w*C4 + c4)
    long base = (long)b * PER_B_ELEMS + rem;

    float4 m = make_float4(-__FLT_MAX__, -__FLT_MAX__, -__FLT_MAX__, -__FLT_MAX__);

    // h = 127 .. 0, suffix max. Unroll 4 so the compiler batches 4 independent
    // LDG.128 ahead of the dependent FMNMX chain (MLP for latency hiding).
    #pragma unroll 4
    for (int h = H - 1; h >= 0; --h) {
        long idx = base + (long)h * STRIDE_H;
        float4 v = in[idx];
        m.x = fmaxf(m.x, v.x);
        m.y = fmaxf(m.y, v.y);
        m.z = fmaxf(m.z, v.z);
        m.w = fmaxf(m.w, v.w);
        out[idx] = m;
    }
}

extern "C" void kernel_launch(void* const* d_in, const int* in_sizes, int n_in,
                              void* d_out, int out_size)
{
    (void)in_sizes; (void)n_in; (void)out_size;
    const float4* in  = (const float4*)d_in[0];
    float4*       out = (float4*)d_out;

    const int threads = 256;
    const int blocks  = (COLS + threads - 1) / threads;  // 512
    rev_cummax_kernel<<<blocks, threads>>>(in, out);
}